// round 2
// baseline (speedup 1.0000x reference)
#include <cuda_runtime.h>
#include <cuda_bf16.h>
#include <math.h>

// Problem constants
#define Bn 8
#define Nn 256
#define Dn 512
#define Hh 16
#define Kk 4
#define DK 32
#define FFN 2048
#define MROWS (Bn*Nn)          // 2048
#define NEGV (-1e12f)

// ---------------- scratch (device globals; no allocation allowed) -------------
__device__ float g_q[Bn*Hh*Nn*DK];        // 4MB  [B,H,N,dk]
__device__ float g_k[Bn*Hh*Nn*DK];
__device__ float g_v[Bn*Hh*Nn*DK];
__device__ float g_acomb[Bn*Kk*Nn*Nn];    // 8MB  combined bias+mask
__device__ float g_msg[MROWS*2048];       // 16MB scrambled msg2 [B*N, K*D]
__device__ float g_h1[MROWS*Dn];          // silu(msg@W1+b1)
__device__ float g_h2[MROWS*Dn];          // h1@W2+b2
__device__ float g_y [MROWS*Dn];          // LN(h2+x)
__device__ float g_f1[MROWS*FFN];         // gelu(y@Wf1+bf1)
__device__ float g_f2[MROWS*Dn];          // f1@Wf2+bf2

// ---------------- prep: combined bias + padding mask + distance mask ---------
__global__ void prep_acomb(const float* __restrict__ dist,
                           const float* __restrict__ dist_bar,
                           const float* __restrict__ bias,
                           const int*   __restrict__ mask)
{
    int n  = blockIdx.y;          // 0..255
    int bk = blockIdx.x;          // 0..31
    int b  = bk >> 2, kk = bk & 3;
    int m  = threadIdx.x;         // 0..255

    int mv = mask[(b*Nn + n)*Nn + m];
    bool dist_ok;
    if (n == 0 || m == 0) dist_ok = true;
    else dist_ok = dist[b*255*255 + (n-1)*255 + (m-1)] < dist_bar[kk];

    float val;
    if (mv != 0 && dist_ok)
        val = bias[((b*Kk + kk)*Nn + n)*Nn + m];
    else
        val = NEGV;
    g_acomb[((b*Kk + kk)*Nn + n)*Nn + m] = val;
}

// ---------------- generic fp32 tiled GEMM: C = epi(A@B + bias) ---------------
// A [M,K] row-major, B [K,N] row-major. BM=128 BN=64 BK=16, 256 thr, 8x4 micro.
#define BM 128
#define BN 64
#define BK 16
#define ASTRIDE 132   // 132*4 = 528 bytes, multiple of 16 -> float4-aligned rows

// EPI: 0 = none, 1 = silu, 2 = gelu(exact erf), 3 = none + QKV layout remap
template<int EPI>
__global__ void __launch_bounds__(256)
gemm_kernel(const float* __restrict__ A, const float* __restrict__ Bw,
            const float* __restrict__ bias, float* __restrict__ C,
            int M, int N, int K)
{
    __shared__ float As[BK*ASTRIDE];
    __shared__ float Bs[BK*BN];

    int t  = threadIdx.x;
    int tx = t & 15, ty = t >> 4;
    int bm = blockIdx.y * BM, bn = blockIdx.x * BN;

    float acc[8][4];
    #pragma unroll
    for (int i = 0; i < 8; i++)
        #pragma unroll
        for (int j = 0; j < 4; j++) acc[i][j] = 0.f;

    int ar = t >> 2;            // 0..63  (A-load row within half-tile)
    int ak = (t & 3) * 4;       // 0,4,8,12
    int br = t >> 4;            // 0..15  (B-load row)
    int bc = (t & 15) * 4;

    for (int k0 = 0; k0 < K; k0 += BK) {
        #pragma unroll
        for (int p = 0; p < 2; p++) {
            int row = ar + p*64;
            float4 av = *(const float4*)&A[(size_t)(bm+row)*K + k0 + ak];
            As[(ak+0)*ASTRIDE + row] = av.x;
            As[(ak+1)*ASTRIDE + row] = av.y;
            As[(ak+2)*ASTRIDE + row] = av.z;
            As[(ak+3)*ASTRIDE + row] = av.w;
        }
        *(float4*)&Bs[br*BN + bc] = *(const float4*)&Bw[(size_t)(k0+br)*N + bn + bc];
        __syncthreads();

        #pragma unroll
        for (int k = 0; k < BK; k++) {
            float4 a0 = *(const float4*)&As[k*ASTRIDE + ty*8];
            float4 a1 = *(const float4*)&As[k*ASTRIDE + ty*8 + 4];
            float4 bf = *(const float4*)&Bs[k*BN + tx*4];
            float aa[8] = {a0.x,a0.y,a0.z,a0.w,a1.x,a1.y,a1.z,a1.w};
            float bb[4] = {bf.x,bf.y,bf.z,bf.w};
            #pragma unroll
            for (int i = 0; i < 8; i++)
                #pragma unroll
                for (int j = 0; j < 4; j++)
                    acc[i][j] += aa[i]*bb[j];
        }
        __syncthreads();
    }

    #pragma unroll
    for (int i = 0; i < 8; i++) {
        int m = bm + ty*8 + i;
        #pragma unroll
        for (int j = 0; j < 4; j++) {
            int c = bn + tx*4 + j;
            float v = acc[i][j] + bias[c];
            if (EPI == 1) v = v / (1.f + __expf(-v));                       // silu
            if (EPI == 2) v = 0.5f * v * (1.f + erff(v * 0.70710678118654752f)); // gelu exact
            if (EPI == 3) {
                int b = m >> 8, n = m & 255, h = c >> 5, d = c & 31;
                C[((b*Hh + h)*Nn + n)*DK + d] = v;
            } else {
                C[(size_t)m*N + c] = v;
            }
        }
    }
}

// ---------------- attention: per (b,h,scale) block, online softmax -----------
// smem: ksm[256*32] + vsm[256*32] + atile[256*33] floats = 99328 bytes
__global__ void __launch_bounds__(256)
attn_kernel()
{
    extern __shared__ float smem[];
    float* ksm   = smem;               // 8192
    float* vsm   = smem + 8192;        // 8192
    float* atile = smem + 16384;       // 256*33

    int kk = blockIdx.x;   // scale
    int h  = blockIdx.y;
    int b  = blockIdx.z;
    int t  = threadIdx.x;  // query row n

    const float* kb = g_k + (size_t)(b*Hh + h)*Nn*DK;
    const float* vb = g_v + (size_t)(b*Hh + h)*Nn*DK;
    const float* qb = g_q + (size_t)(b*Hh + h)*Nn*DK;

    // cooperative load K,V (coalesced float4)
    {
        const float4* k4 = (const float4*)kb;
        const float4* v4 = (const float4*)vb;
        float4* ks4 = (float4*)ksm;
        float4* vs4 = (float4*)vsm;
        #pragma unroll
        for (int i = 0; i < 8; i++) {
            ks4[i*256 + t] = k4[i*256 + t];
            vs4[i*256 + t] = v4[i*256 + t];
        }
    }
    // per-thread query row
    float qreg[DK];
    {
        const float4* q4 = (const float4*)(qb + t*DK);
        #pragma unroll
        for (int i = 0; i < 8; i++) {
            float4 v = q4[i];
            qreg[i*4+0]=v.x; qreg[i*4+1]=v.y; qreg[i*4+2]=v.z; qreg[i*4+3]=v.w;
        }
    }
    __syncthreads();

    const float inv_sqrt = 0.17677669529663688f;   // 1/sqrt(32)
    float mx = -INFINITY, sum = 0.f;
    float accv[DK];
    #pragma unroll
    for (int d = 0; d < DK; d++) accv[d] = 0.f;

    const float* abase = g_acomb + (size_t)((b*Kk + kk)*Nn)*Nn;

    for (int m0 = 0; m0 < Nn; m0 += 32) {
        __syncthreads();
        // stage combined bias tile [256 n][32 m] coalesced
        #pragma unroll
        for (int i = 0; i < 32; i++) {
            int idx = i*256 + t;
            int nrow = idx >> 5, ml = idx & 31;
            atile[nrow*33 + ml] = abase[(size_t)nrow*Nn + m0 + ml];
        }
        __syncthreads();

        float sreg[32];
        float cmax = -INFINITY;
        #pragma unroll
        for (int ml = 0; ml < 32; ml++) {
            int m = m0 + ml;
            const float4* kr = (const float4*)(ksm + m*DK);
            float s = 0.f;
            #pragma unroll
            for (int i = 0; i < 8; i++) {
                float4 kv = kr[i];
                s += qreg[i*4+0]*kv.x + qreg[i*4+1]*kv.y
                   + qreg[i*4+2]*kv.z + qreg[i*4+3]*kv.w;
            }
            s = s * inv_sqrt + atile[t*33 + ml];
            sreg[ml] = s;
            cmax = fmaxf(cmax, s);
        }
        float newmax = fmaxf(mx, cmax);
        float corr = __expf(mx - newmax);     // exp(-inf)=0 on first chunk
        sum *= corr;
        #pragma unroll
        for (int d = 0; d < DK; d++) accv[d] *= corr;
        #pragma unroll
        for (int ml = 0; ml < 32; ml++) {
            float p = __expf(sreg[ml] - newmax);
            sum += p;
            const float4* vr = (const float4*)(vsm + (m0+ml)*DK);
            #pragma unroll
            for (int i = 0; i < 8; i++) {
                float4 vv = vr[i];
                accv[i*4+0] += p*vv.x; accv[i*4+1] += p*vv.y;
                accv[i*4+2] += p*vv.z; accv[i*4+3] += p*vv.w;
            }
        }
        mx = newmax;
    }

    float inv = 1.f / sum;
    // scrambled reshape: msg2[b, n2, f], n2 = (kk*H+h)*4 + (d>>3), f = (d&7)*256 + n
    int khbase = (kk*Hh + h) * 4;
    #pragma unroll
    for (int d = 0; d < DK; d++) {
        int n2 = khbase + (d >> 3);
        int f  = (d & 7)*256 + t;
        g_msg[((size_t)(b*Nn) + n2)*2048 + f] = accv[d]*inv;
    }
}

// ---------------- add-residual + LayerNorm (rows of 512) ---------------------
__global__ void __launch_bounds__(256)
ln_kernel(const float* __restrict__ a, const float* __restrict__ resid,
          const float* __restrict__ g, const float* __restrict__ be,
          float* __restrict__ out)
{
    int row = blockIdx.x;
    int t   = threadIdx.x;
    const float* ap = a + (size_t)row*Dn;
    const float* rp = resid + (size_t)row*Dn;
    float v0 = ap[t]     + rp[t];
    float v1 = ap[t+256] + rp[t+256];

    float s  = v0 + v1;
    float sq = v0*v0 + v1*v1;
    // warp reduce
    #pragma unroll
    for (int o = 16; o > 0; o >>= 1) {
        s  += __shfl_xor_sync(0xffffffffu, s,  o);
        sq += __shfl_xor_sync(0xffffffffu, sq, o);
    }
    __shared__ float ws[8], wq[8], stat[2];
    int warp = t >> 5, lane = t & 31;
    if (lane == 0) { ws[warp] = s; wq[warp] = sq; }
    __syncthreads();
    if (t == 0) {
        float ts = 0.f, tq = 0.f;
        #pragma unroll
        for (int i = 0; i < 8; i++) { ts += ws[i]; tq += wq[i]; }
        float mean = ts * (1.f/Dn);
        float var  = tq * (1.f/Dn) - mean*mean;
        stat[0] = mean;
        stat[1] = rsqrtf(var + 1e-6f);
    }
    __syncthreads();
    float mean = stat[0], inv = stat[1];
    out[(size_t)row*Dn + t]       = (v0 - mean)*inv*g[t]       + be[t];
    out[(size_t)row*Dn + t + 256] = (v1 - mean)*inv*g[t+256]   + be[t+256];
}

// ---------------- launch ------------------------------------------------------
extern "C" void kernel_launch(void* const* d_in, const int* in_sizes, int n_in,
                              void* d_out, int out_size)
{
    const float* x    = (const float*)d_in[0];
    const float* dist = (const float*)d_in[1];
    const float* dbar = (const float*)d_in[2];
    const float* ab   = (const float*)d_in[3];
    const int*   mask = (const int*)  d_in[4];
    // d_in[5] = num_heads (fixed 16)
    const float* Wq = (const float*)d_in[6],  *bq = (const float*)d_in[7];
    const float* Wk = (const float*)d_in[8],  *bk = (const float*)d_in[9];
    const float* Wv = (const float*)d_in[10], *bv = (const float*)d_in[11];
    const float* W1 = (const float*)d_in[12], *b1 = (const float*)d_in[13];
    const float* W2 = (const float*)d_in[14], *b2 = (const float*)d_in[15];
    const float* g1 = (const float*)d_in[16], *be1= (const float*)d_in[17];
    const float* Wf1= (const float*)d_in[18], *bf1= (const float*)d_in[19];
    const float* Wf2= (const float*)d_in[20], *bf2= (const float*)d_in[21];
    const float* g2 = (const float*)d_in[22], *be2= (const float*)d_in[23];
    float* out = (float*)d_out;

    float *pq, *pk, *pv, *pmsg, *ph1, *ph2, *py, *pf1, *pf2;
    cudaGetSymbolAddress((void**)&pq,  g_q);
    cudaGetSymbolAddress((void**)&pk,  g_k);
    cudaGetSymbolAddress((void**)&pv,  g_v);
    cudaGetSymbolAddress((void**)&pmsg,g_msg);
    cudaGetSymbolAddress((void**)&ph1, g_h1);
    cudaGetSymbolAddress((void**)&ph2, g_h2);
    cudaGetSymbolAddress((void**)&py,  g_y);
    cudaGetSymbolAddress((void**)&pf1, g_f1);
    cudaGetSymbolAddress((void**)&pf2, g_f2);

    const int ATTN_SMEM = (8192 + 8192 + 256*33) * 4;   // 99328 B
    cudaFuncSetAttribute(attn_kernel,
                         cudaFuncAttributeMaxDynamicSharedMemorySize, ATTN_SMEM);

    // 1. combined bias/mask
    prep_acomb<<<dim3(Bn*Kk, Nn), 256>>>(dist, dbar, ab, mask);

    // 2. QKV projections -> [B,H,N,dk]
    {
        dim3 grid(Dn/BN, MROWS/BM);
        gemm_kernel<3><<<grid, 256>>>(x, Wq, bq, pq, MROWS, Dn, Dn);
        gemm_kernel<3><<<grid, 256>>>(x, Wk, bk, pk, MROWS, Dn, Dn);
        gemm_kernel<3><<<grid, 256>>>(x, Wv, bv, pv, MROWS, Dn, Dn);
    }

    // 3. attention (writes scrambled msg2 directly)
    attn_kernel<<<dim3(Kk, Hh, Bn), 256, ATTN_SMEM>>>();

    // 4. h1 = silu(msg2 @ W1 + b1)      [2048,2048]@[2048,512]
    gemm_kernel<1><<<dim3(Dn/BN, MROWS/BM), 256>>>(pmsg, W1, b1, ph1, MROWS, Dn, 2048);
    // 5. h2 = h1 @ W2 + b2              [2048,512]@[512,512]
    gemm_kernel<0><<<dim3(Dn/BN, MROWS/BM), 256>>>(ph1, W2, b2, ph2, MROWS, Dn, Dn);
    // 6. y = LN(h2 + x)
    ln_kernel<<<MROWS, 256>>>(ph2, x, g1, be1, py);
    // 7. f1 = gelu(y @ Wf1 + bf1)       [2048,512]@[512,2048]
    gemm_kernel<2><<<dim3(FFN/BN, MROWS/BM), 256>>>(py, Wf1, bf1, pf1, MROWS, FFN, Dn);
    // 8. f2 = f1 @ Wf2 + bf2            [2048,2048]@[2048,512]
    gemm_kernel<0><<<dim3(Dn/BN, MROWS/BM), 256>>>(pf1, Wf2, bf2, pf2, MROWS, Dn, 2048);
    // 9. out = LN(f2 + y)
    ln_kernel<<<MROWS, 256>>>(pf2, py, g2, be2, out);
}

// round 3
// speedup vs baseline: 1.8120x; 1.8120x over previous
#include <cuda_runtime.h>
#include <cuda_bf16.h>
#include <math.h>
#include <stdint.h>

// Problem constants
#define Bn 8
#define Nn 256
#define Dn 512
#define Hh 16
#define Kk 4
#define DK 32
#define FFN 2048
#define MROWS (Bn*Nn)          // 2048
#define NEGV (-1e12f)

// ---------------- scratch (device globals; no allocation allowed) -------------
__device__ float g_q[Bn*Hh*Nn*DK];        // [B,H,N,dk]
__device__ float g_k[Bn*Hh*Nn*DK];
__device__ float g_v[Bn*Hh*Nn*DK];
__device__ float g_acomb[Bn*Kk*Nn*Nn];    // combined bias+mask
__device__ float g_msg[MROWS*2048];       // scrambled msg2 [B*N, K*D]
__device__ float g_h1[MROWS*Dn];
__device__ float g_h2[MROWS*Dn];
__device__ float g_y [MROWS*Dn];
__device__ float g_f1[MROWS*FFN];
__device__ float g_f2[MROWS*Dn];

// ---------------- prep: combined bias + padding mask + distance mask ---------
__global__ void prep_acomb(const float* __restrict__ dist,
                           const float* __restrict__ dist_bar,
                           const float* __restrict__ bias,
                           const int*   __restrict__ mask)
{
    int n  = blockIdx.y;          // 0..255
    int bk = blockIdx.x;          // 0..31
    int b  = bk >> 2, kk = bk & 3;
    int m  = threadIdx.x;         // 0..255

    int mv = mask[(b*Nn + n)*Nn + m];
    bool dist_ok;
    if (n == 0 || m == 0) dist_ok = true;
    else dist_ok = dist[b*255*255 + (n-1)*255 + (m-1)] < dist_bar[kk];

    float val;
    if (mv != 0 && dist_ok)
        val = bias[((b*Kk + kk)*Nn + n)*Nn + m];
    else
        val = NEGV;
    g_acomb[((b*Kk + kk)*Nn + n)*Nn + m] = val;
}

// =====================  tf32 tensor-core GEMM  ================================
// C = epi(A@B + bias).  A [M,K] row-major, B [K,N] row-major.
// Block tile 128x128, BK=32, 256 threads (8 warps, 4x2, warptile 32x64).
// Double-buffered cp.async.  smem: A[2][128*36] + B[2][32*136] = 71680 B.

#define GSMEM_BYTES 71680
#define AS_STRIDE 36
#define BS_STRIDE 136
#define AS_TILE (128*AS_STRIDE)   // 4608 floats
#define BS_TILE (32*BS_STRIDE)    // 4352 floats

__device__ __forceinline__ uint32_t cvta_s(const void* p) {
    return (uint32_t)__cvta_generic_to_shared(p);
}
#define CPA16(dst, src) \
    asm volatile("cp.async.cg.shared.global [%0], [%1], 16;" :: "r"(dst), "l"(src))

__device__ __forceinline__ uint32_t f2tf(float f) {
    uint32_t r; asm("cvt.rna.tf32.f32 %0, %1;" : "=r"(r) : "f"(f)); return r;
}
__device__ __forceinline__ void mma8(float c[4], const uint32_t a[4], const uint32_t b[2]) {
    asm volatile(
      "mma.sync.aligned.m16n8k8.row.col.f32.tf32.tf32.f32 "
      "{%0,%1,%2,%3},{%4,%5,%6,%7},{%8,%9},{%0,%1,%2,%3};"
      : "+f"(c[0]), "+f"(c[1]), "+f"(c[2]), "+f"(c[3])
      : "r"(a[0]), "r"(a[1]), "r"(a[2]), "r"(a[3]), "r"(b[0]), "r"(b[1]));
}

// Core: accumulate block tile (bm,bn) into acc[2][8][4]
__device__ __forceinline__ void mma_core(const float* __restrict__ A,
                                         const float* __restrict__ Bw,
                                         float* smem, int N, int K,
                                         int bm, int bn, float acc[2][8][4])
{
    float* As = smem;
    float* Bs = smem + 2*AS_TILE;
    int t = threadIdx.x, lane = t & 31, warp = t >> 5;
    int g = lane >> 2, tid4 = lane & 3;
    int wm = (warp >> 1) * 32, wn = (warp & 1) * 64;

    int T = K / 32;

    auto copy_tile = [&](int kt, int buf) {
        float* Ad = As + buf*AS_TILE;
        float* Bd = Bs + buf*BS_TILE;
        int k0 = kt * 32;
        #pragma unroll
        for (int i = 0; i < 4; i++) {
            int idx = t + i*256;
            int row = idx >> 3, f4 = (idx & 7) * 4;
            CPA16(cvta_s(Ad + row*AS_STRIDE + f4),
                  A + (size_t)(bm + row)*K + k0 + f4);
        }
        #pragma unroll
        for (int i = 0; i < 4; i++) {
            int idx = t + i*256;
            int r = idx >> 5, f4 = (idx & 31) * 4;
            CPA16(cvta_s(Bd + r*BS_STRIDE + f4),
                  Bw + (size_t)(k0 + r)*N + bn + f4);
        }
        asm volatile("cp.async.commit_group;");
    };

    copy_tile(0, 0);
    for (int kt = 0; kt < T; kt++) {
        int buf = kt & 1;
        if (kt + 1 < T) {
            copy_tile(kt + 1, buf ^ 1);
            asm volatile("cp.async.wait_group 1;");
        } else {
            asm volatile("cp.async.wait_group 0;");
        }
        __syncthreads();

        const float* Ab = As + buf*AS_TILE;
        const float* Bb = Bs + buf*BS_TILE;
        #pragma unroll
        for (int ks = 0; ks < 4; ks++) {
            int kk = ks * 8;
            uint32_t af[2][4], bf[8][2];
            #pragma unroll
            for (int mf = 0; mf < 2; mf++) {
                const float* p = Ab + (wm + mf*16 + g)*AS_STRIDE + kk + tid4;
                af[mf][0] = f2tf(p[0]);
                af[mf][1] = f2tf(p[8*AS_STRIDE]);
                af[mf][2] = f2tf(p[4]);
                af[mf][3] = f2tf(p[8*AS_STRIDE + 4]);
            }
            #pragma unroll
            for (int nf = 0; nf < 8; nf++) {
                const float* p = Bb + (kk + tid4)*BS_STRIDE + wn + nf*8 + g;
                bf[nf][0] = f2tf(p[0]);
                bf[nf][1] = f2tf(p[4*BS_STRIDE]);
            }
            #pragma unroll
            for (int mf = 0; mf < 2; mf++)
                #pragma unroll
                for (int nf = 0; nf < 8; nf++)
                    mma8(acc[mf][nf], af[mf], bf[nf]);
        }
        __syncthreads();
    }
}

// EPI: 0 = none, 1 = silu, 2 = gelu(exact erf)
template<int EPI>
__global__ void __launch_bounds__(256)
mma_gemm(const float* __restrict__ A, const float* __restrict__ Bw,
         const float* __restrict__ bias, float* __restrict__ C, int N, int K)
{
    extern __shared__ float smem[];
    float acc[2][8][4];
    #pragma unroll
    for (int i = 0; i < 2; i++)
        #pragma unroll
        for (int j = 0; j < 8; j++)
            #pragma unroll
            for (int q = 0; q < 4; q++) acc[i][j][q] = 0.f;

    int bm = blockIdx.y * 128, bn = blockIdx.x * 128;
    mma_core(A, Bw, smem, N, K, bm, bn, acc);

    int lane = threadIdx.x & 31, warp = threadIdx.x >> 5;
    int g = lane >> 2, tid4 = lane & 3;
    int wm = (warp >> 1) * 32, wn = (warp & 1) * 64;

    #pragma unroll
    for (int mf = 0; mf < 2; mf++)
        #pragma unroll
        for (int nf = 0; nf < 8; nf++)
            #pragma unroll
            for (int r = 0; r < 2; r++)
                #pragma unroll
                for (int c = 0; c < 2; c++) {
                    int row = bm + wm + mf*16 + g + r*8;
                    int col = bn + wn + nf*8 + tid4*2 + c;
                    float v = acc[mf][nf][r*2 + c] + bias[col];
                    if (EPI == 1) v = v / (1.f + __expf(-v));
                    if (EPI == 2) v = 0.5f * v * (1.f + erff(v * 0.70710678118654752f));
                    C[(size_t)row*N + col] = v;
                }
}

// Fused QKV: blockIdx.z selects {Wq,Wk,Wv}; epilogue remaps to [B,H,N,dk]
__global__ void __launch_bounds__(256)
mma_gemm_qkv(const float* __restrict__ A,
             const float* Wq, const float* Wk, const float* Wv,
             const float* bq, const float* bk, const float* bv,
             float* oq, float* ok, float* ov)
{
    extern __shared__ float smem[];
    const float* Bw   = blockIdx.z == 0 ? Wq : (blockIdx.z == 1 ? Wk : Wv);
    const float* bias = blockIdx.z == 0 ? bq : (blockIdx.z == 1 ? bk : bv);
    float*       O    = blockIdx.z == 0 ? oq : (blockIdx.z == 1 ? ok : ov);

    float acc[2][8][4];
    #pragma unroll
    for (int i = 0; i < 2; i++)
        #pragma unroll
        for (int j = 0; j < 8; j++)
            #pragma unroll
            for (int q = 0; q < 4; q++) acc[i][j][q] = 0.f;

    int bm = blockIdx.y * 128, bn = blockIdx.x * 128;
    mma_core(A, Bw, smem, Dn, Dn, bm, bn, acc);

    int lane = threadIdx.x & 31, warp = threadIdx.x >> 5;
    int g = lane >> 2, tid4 = lane & 3;
    int wm = (warp >> 1) * 32, wn = (warp & 1) * 64;

    #pragma unroll
    for (int mf = 0; mf < 2; mf++)
        #pragma unroll
        for (int nf = 0; nf < 8; nf++)
            #pragma unroll
            for (int r = 0; r < 2; r++)
                #pragma unroll
                for (int c = 0; c < 2; c++) {
                    int row = bm + wm + mf*16 + g + r*8;
                    int col = bn + wn + nf*8 + tid4*2 + c;
                    float v = acc[mf][nf][r*2 + c] + bias[col];
                    int b = row >> 8, n = row & 255, h = col >> 5, d = col & 31;
                    O[((b*Hh + h)*Nn + n)*DK + d] = v;
                }
}

// ---------------- attention: per (b,h,scale) block, online softmax -----------
__global__ void __launch_bounds__(256)
attn_kernel()
{
    extern __shared__ float smem[];
    float* ksm   = smem;               // 8192
    float* vsm   = smem + 8192;        // 8192
    float* atile = smem + 16384;       // 256*33

    int kk = blockIdx.x;   // scale
    int h  = blockIdx.y;
    int b  = blockIdx.z;
    int t  = threadIdx.x;  // query row n

    const float* kb = g_k + (size_t)(b*Hh + h)*Nn*DK;
    const float* vb = g_v + (size_t)(b*Hh + h)*Nn*DK;
    const float* qb = g_q + (size_t)(b*Hh + h)*Nn*DK;

    {
        const float4* k4 = (const float4*)kb;
        const float4* v4 = (const float4*)vb;
        float4* ks4 = (float4*)ksm;
        float4* vs4 = (float4*)vsm;
        #pragma unroll
        for (int i = 0; i < 8; i++) {
            ks4[i*256 + t] = k4[i*256 + t];
            vs4[i*256 + t] = v4[i*256 + t];
        }
    }
    float qreg[DK];
    {
        const float4* q4 = (const float4*)(qb + t*DK);
        #pragma unroll
        for (int i = 0; i < 8; i++) {
            float4 v = q4[i];
            qreg[i*4+0]=v.x; qreg[i*4+1]=v.y; qreg[i*4+2]=v.z; qreg[i*4+3]=v.w;
        }
    }
    __syncthreads();

    const float inv_sqrt = 0.17677669529663688f;   // 1/sqrt(32)
    float mx = -INFINITY, sum = 0.f;
    float accv[DK];
    #pragma unroll
    for (int d = 0; d < DK; d++) accv[d] = 0.f;

    const float* abase = g_acomb + (size_t)((b*Kk + kk)*Nn)*Nn;

    for (int m0 = 0; m0 < Nn; m0 += 32) {
        __syncthreads();
        #pragma unroll
        for (int i = 0; i < 32; i++) {
            int idx = i*256 + t;
            int nrow = idx >> 5, ml = idx & 31;
            atile[nrow*33 + ml] = abase[(size_t)nrow*Nn + m0 + ml];
        }
        __syncthreads();

        float sreg[32];
        float cmax = -INFINITY;
        #pragma unroll
        for (int ml = 0; ml < 32; ml++) {
            int m = m0 + ml;
            const float4* kr = (const float4*)(ksm + m*DK);
            float s = 0.f;
            #pragma unroll
            for (int i = 0; i < 8; i++) {
                float4 kv = kr[i];
                s += qreg[i*4+0]*kv.x + qreg[i*4+1]*kv.y
                   + qreg[i*4+2]*kv.z + qreg[i*4+3]*kv.w;
            }
            s = s * inv_sqrt + atile[t*33 + ml];
            sreg[ml] = s;
            cmax = fmaxf(cmax, s);
        }
        float newmax = fmaxf(mx, cmax);
        float corr = __expf(mx - newmax);
        sum *= corr;
        #pragma unroll
        for (int d = 0; d < DK; d++) accv[d] *= corr;
        #pragma unroll
        for (int ml = 0; ml < 32; ml++) {
            float p = __expf(sreg[ml] - newmax);
            sum += p;
            const float4* vr = (const float4*)(vsm + (m0+ml)*DK);
            #pragma unroll
            for (int i = 0; i < 8; i++) {
                float4 vv = vr[i];
                accv[i*4+0] += p*vv.x; accv[i*4+1] += p*vv.y;
                accv[i*4+2] += p*vv.z; accv[i*4+3] += p*vv.w;
            }
        }
        mx = newmax;
    }

    float inv = 1.f / sum;
    int khbase = (kk*Hh + h) * 4;
    #pragma unroll
    for (int d = 0; d < DK; d++) {
        int n2 = khbase + (d >> 3);
        int f  = (d & 7)*256 + t;
        g_msg[((size_t)(b*Nn) + n2)*2048 + f] = accv[d]*inv;
    }
}

// ---------------- add-residual + LayerNorm (rows of 512) ---------------------
__global__ void __launch_bounds__(256)
ln_kernel(const float* __restrict__ a, const float* __restrict__ resid,
          const float* __restrict__ g, const float* __restrict__ be,
          float* __restrict__ out)
{
    int row = blockIdx.x;
    int t   = threadIdx.x;
    const float* ap = a + (size_t)row*Dn;
    const float* rp = resid + (size_t)row*Dn;
    float v0 = ap[t]     + rp[t];
    float v1 = ap[t+256] + rp[t+256];

    float s  = v0 + v1;
    float sq = v0*v0 + v1*v1;
    #pragma unroll
    for (int o = 16; o > 0; o >>= 1) {
        s  += __shfl_xor_sync(0xffffffffu, s,  o);
        sq += __shfl_xor_sync(0xffffffffu, sq, o);
    }
    __shared__ float ws[8], wq[8], stat[2];
    int warp = t >> 5, lane = t & 31;
    if (lane == 0) { ws[warp] = s; wq[warp] = sq; }
    __syncthreads();
    if (t == 0) {
        float ts = 0.f, tq = 0.f;
        #pragma unroll
        for (int i = 0; i < 8; i++) { ts += ws[i]; tq += wq[i]; }
        float mean = ts * (1.f/Dn);
        float var  = tq * (1.f/Dn) - mean*mean;
        stat[0] = mean;
        stat[1] = rsqrtf(var + 1e-6f);
    }
    __syncthreads();
    float mean = stat[0], inv = stat[1];
    out[(size_t)row*Dn + t]       = (v0 - mean)*inv*g[t]       + be[t];
    out[(size_t)row*Dn + t + 256] = (v1 - mean)*inv*g[t+256]   + be[t+256];
}

// ---------------- launch ------------------------------------------------------
extern "C" void kernel_launch(void* const* d_in, const int* in_sizes, int n_in,
                              void* d_out, int out_size)
{
    const float* x    = (const float*)d_in[0];
    const float* dist = (const float*)d_in[1];
    const float* dbar = (const float*)d_in[2];
    const float* ab   = (const float*)d_in[3];
    const int*   mask = (const int*)  d_in[4];
    const float* Wq = (const float*)d_in[6],  *bq = (const float*)d_in[7];
    const float* Wk = (const float*)d_in[8],  *bk = (const float*)d_in[9];
    const float* Wv = (const float*)d_in[10], *bv = (const float*)d_in[11];
    const float* W1 = (const float*)d_in[12], *b1 = (const float*)d_in[13];
    const float* W2 = (const float*)d_in[14], *b2 = (const float*)d_in[15];
    const float* g1 = (const float*)d_in[16], *be1= (const float*)d_in[17];
    const float* Wf1= (const float*)d_in[18], *bf1= (const float*)d_in[19];
    const float* Wf2= (const float*)d_in[20], *bf2= (const float*)d_in[21];
    const float* g2 = (const float*)d_in[22], *be2= (const float*)d_in[23];
    float* out = (float*)d_out;

    float *pq, *pk, *pv, *pmsg, *ph1, *ph2, *py, *pf1, *pf2;
    cudaGetSymbolAddress((void**)&pq,  g_q);
    cudaGetSymbolAddress((void**)&pk,  g_k);
    cudaGetSymbolAddress((void**)&pv,  g_v);
    cudaGetSymbolAddress((void**)&pmsg,g_msg);
    cudaGetSymbolAddress((void**)&ph1, g_h1);
    cudaGetSymbolAddress((void**)&ph2, g_h2);
    cudaGetSymbolAddress((void**)&py,  g_y);
    cudaGetSymbolAddress((void**)&pf1, g_f1);
    cudaGetSymbolAddress((void**)&pf2, g_f2);

    const int ATTN_SMEM = (8192 + 8192 + 256*33) * 4;   // 99328 B
    cudaFuncSetAttribute(attn_kernel,
                         cudaFuncAttributeMaxDynamicSharedMemorySize, ATTN_SMEM);
    cudaFuncSetAttribute(mma_gemm_qkv,
                         cudaFuncAttributeMaxDynamicSharedMemorySize, GSMEM_BYTES);
    cudaFuncSetAttribute(mma_gemm<0>,
                         cudaFuncAttributeMaxDynamicSharedMemorySize, GSMEM_BYTES);
    cudaFuncSetAttribute(mma_gemm<1>,
                         cudaFuncAttributeMaxDynamicSharedMemorySize, GSMEM_BYTES);
    cudaFuncSetAttribute(mma_gemm<2>,
                         cudaFuncAttributeMaxDynamicSharedMemorySize, GSMEM_BYTES);

    // 1. combined bias/mask
    prep_acomb<<<dim3(Bn*Kk, Nn), 256>>>(dist, dbar, ab, mask);

    // 2. fused QKV projections -> [B,H,N,dk]  (tf32 tensor cores)
    mma_gemm_qkv<<<dim3(Dn/128, MROWS/128, 3), 256, GSMEM_BYTES>>>(
        x, Wq, Wk, Wv, bq, bk, bv, pq, pk, pv);

    // 3. attention (writes scrambled msg2 directly)
    attn_kernel<<<dim3(Kk, Hh, Bn), 256, ATTN_SMEM>>>();

    // 4. h1 = silu(msg2 @ W1 + b1)
    mma_gemm<1><<<dim3(Dn/128, MROWS/128), 256, GSMEM_BYTES>>>(pmsg, W1, b1, ph1, Dn, 2048);
    // 5. h2 = h1 @ W2 + b2
    mma_gemm<0><<<dim3(Dn/128, MROWS/128), 256, GSMEM_BYTES>>>(ph1, W2, b2, ph2, Dn, Dn);
    // 6. y = LN(h2 + x)
    ln_kernel<<<MROWS, 256>>>(ph2, x, g1, be1, py);
    // 7. f1 = gelu(y @ Wf1 + bf1)
    mma_gemm<2><<<dim3(FFN/128, MROWS/128), 256, GSMEM_BYTES>>>(py, Wf1, bf1, pf1, FFN, Dn);
    // 8. f2 = f1 @ Wf2 + bf2
    mma_gemm<0><<<dim3(Dn/128, MROWS/128), 256, GSMEM_BYTES>>>(pf1, Wf2, bf2, pf2, Dn, 2048);
    // 9. out = LN(f2 + y)
    ln_kernel<<<MROWS, 256>>>(pf2, py, g2, be2, out);
}

// round 4
// speedup vs baseline: 2.0057x; 1.1069x over previous
#include <cuda_runtime.h>
#include <cuda_bf16.h>
#include <math.h>
#include <stdint.h>

// Problem constants
#define Bn 8
#define Nn 256
#define Dn 512
#define Hh 16
#define Kk 4
#define DK 32
#define FFN 2048
#define MROWS (Bn*Nn)          // 2048
#define NEGV (-1e12f)

// ---------------- scratch (device globals; no allocation allowed) -------------
__device__ float g_q[Bn*Hh*Nn*DK];        // [B,H,N,dk]
__device__ float g_k[Bn*Hh*Nn*DK];
__device__ float g_v[Bn*Hh*Nn*DK];
__device__ float g_acomb[Bn*Kk*Nn*Nn];    // combined bias+mask
__device__ float g_msg[MROWS*2048];       // scrambled msg2 (tf32-rounded)
__device__ float g_h1[MROWS*Dn];          // silu out (tf32-rounded)
__device__ float g_h2[MROWS*Dn];
__device__ float g_y [MROWS*Dn];          // fp32 (for residual)
__device__ float g_yr[MROWS*Dn];          // tf32-rounded y (for GEMM)
__device__ float g_f1[MROWS*FFN];         // gelu out (tf32-rounded)
__device__ float g_f2[MROWS*Dn];
// tf32-rounded operand copies
__device__ float g_rx [MROWS*Dn];
__device__ float g_rwq[Dn*Dn];
__device__ float g_rwk[Dn*Dn];
__device__ float g_rwv[Dn*Dn];
__device__ float g_rw1[2048*Dn];
__device__ float g_rw2[Dn*Dn];
__device__ float g_rwf1[Dn*FFN];
__device__ float g_rwf2[FFN*Dn];

__device__ __forceinline__ uint32_t f2tf(float f) {
    uint32_t r; asm("cvt.rna.tf32.f32 %0, %1;" : "=r"(r) : "f"(f)); return r;
}
__device__ __forceinline__ float roundtf(float f) { return __uint_as_float(f2tf(f)); }

// ---------------- tf32 pre-rounding pass (8 tensors in one launch) ------------
struct RoundArgs {
    const float* in[8];
    float*       out[8];
    int          n4[8];     // element count / 4
};
__global__ void __launch_bounds__(256)
round_kernel(RoundArgs a)
{
    int j = blockIdx.y;
    const float4* in  = (const float4*)a.in[j];
    float4*       out = (float4*)a.out[j];
    int n4 = a.n4[j];
    for (int i = blockIdx.x*256 + threadIdx.x; i < n4; i += gridDim.x*256) {
        float4 v = in[i];
        v.x = roundtf(v.x); v.y = roundtf(v.y);
        v.z = roundtf(v.z); v.w = roundtf(v.w);
        out[i] = v;
    }
}

// ---------------- prep: combined bias + padding mask + distance mask ---------
__global__ void prep_acomb(const float* __restrict__ dist,
                           const float* __restrict__ dist_bar,
                           const float* __restrict__ bias,
                           const int*   __restrict__ mask)
{
    int n  = blockIdx.y;
    int bk = blockIdx.x;
    int b  = bk >> 2, kk = bk & 3;
    int m  = threadIdx.x;

    int mv = mask[(b*Nn + n)*Nn + m];
    bool dist_ok;
    if (n == 0 || m == 0) dist_ok = true;
    else dist_ok = dist[b*255*255 + (n-1)*255 + (m-1)] < dist_bar[kk];

    float val;
    if (mv != 0 && dist_ok)
        val = bias[((b*Kk + kk)*Nn + n)*Nn + m];
    else
        val = NEGV;
    g_acomb[((b*Kk + kk)*Nn + n)*Nn + m] = val;
}

// =====================  tf32 tensor-core GEMM  ================================
// Operands are PRE-ROUNDED to tf32 (low 13 mantissa bits zero) -> no cvt in loop.
// Block tile 128 x BN, BK=32, 256 threads (8 warps, 4x2).
// Warp tile 32 x (BN/2).  Double-buffered cp.async.

#define AS_STRIDE 36
#define AS_TILE (128*AS_STRIDE)

__device__ __forceinline__ uint32_t cvta_s(const void* p) {
    return (uint32_t)__cvta_generic_to_shared(p);
}
#define CPA16(dst, src) \
    asm volatile("cp.async.cg.shared.global [%0], [%1], 16;" :: "r"(dst), "l"(src))

__device__ __forceinline__ void mma8(float c[4], const uint32_t a[4], const uint32_t b[2]) {
    asm volatile(
      "mma.sync.aligned.m16n8k8.row.col.f32.tf32.tf32.f32 "
      "{%0,%1,%2,%3},{%4,%5,%6,%7},{%8,%9},{%0,%1,%2,%3};"
      : "+f"(c[0]), "+f"(c[1]), "+f"(c[2]), "+f"(c[3])
      : "r"(a[0]), "r"(a[1]), "r"(a[2]), "r"(a[3]), "r"(b[0]), "r"(b[1]));
}

template<int BN>
__device__ __forceinline__ void mma_core(const float* __restrict__ A,
                                         const float* __restrict__ Bw,
                                         float* smem, int N, int K,
                                         int bm, int bn, float acc[2][BN/16][4])
{
    constexpr int BS_STRIDE = BN + 8;
    constexpr int BS_TILE   = 32 * BS_STRIDE;
    constexpr int NF        = BN / 16;

    float* As = smem;
    float* Bs = smem + 2*AS_TILE;
    int t = threadIdx.x, lane = t & 31, warp = t >> 5;
    int g = lane >> 2, tid4 = lane & 3;
    int wm = (warp >> 1) * 32, wn = (warp & 1) * (BN/2);

    int T = K / 32;

    auto copy_tile = [&](int kt, int buf) {
        float* Ad = As + buf*AS_TILE;
        float* Bd = Bs + buf*BS_TILE;
        int k0 = kt * 32;
        #pragma unroll
        for (int i = 0; i < 4; i++) {
            int idx = t + i*256;
            int row = idx >> 3, f4 = (idx & 7) * 4;
            CPA16(cvta_s(Ad + row*AS_STRIDE + f4),
                  A + (size_t)(bm + row)*K + k0 + f4);
        }
        #pragma unroll
        for (int i = 0; i < BN/32; i++) {
            int idx = t + i*256;
            int r = idx / (BN/4), f4 = (idx % (BN/4)) * 4;
            CPA16(cvta_s(Bd + r*BS_STRIDE + f4),
                  Bw + (size_t)(k0 + r)*N + bn + f4);
        }
        asm volatile("cp.async.commit_group;");
    };

    copy_tile(0, 0);
    for (int kt = 0; kt < T; kt++) {
        int buf = kt & 1;
        if (kt + 1 < T) {
            copy_tile(kt + 1, buf ^ 1);
            asm volatile("cp.async.wait_group 1;");
        } else {
            asm volatile("cp.async.wait_group 0;");
        }
        __syncthreads();

        const uint32_t* Ab = (const uint32_t*)(As + buf*AS_TILE);
        const uint32_t* Bb = (const uint32_t*)(Bs + buf*BS_TILE);
        #pragma unroll
        for (int ks = 0; ks < 4; ks++) {
            int kk = ks * 8;
            uint32_t af[2][4], bf[NF][2];
            #pragma unroll
            for (int mf = 0; mf < 2; mf++) {
                const uint32_t* p = Ab + (wm + mf*16 + g)*AS_STRIDE + kk + tid4;
                af[mf][0] = p[0];
                af[mf][1] = p[8*AS_STRIDE];
                af[mf][2] = p[4];
                af[mf][3] = p[8*AS_STRIDE + 4];
            }
            #pragma unroll
            for (int nf = 0; nf < NF; nf++) {
                const uint32_t* p = Bb + (kk + tid4)*BS_STRIDE + wn + nf*8 + g;
                bf[nf][0] = p[0];
                bf[nf][1] = p[4*BS_STRIDE];
            }
            #pragma unroll
            for (int mf = 0; mf < 2; mf++)
                #pragma unroll
                for (int nf = 0; nf < NF; nf++)
                    mma8(acc[mf][nf], af[mf], bf[nf]);
        }
        __syncthreads();
    }
}

// EPI: 0 = none, 1 = silu (tf32-rounded out), 2 = gelu (tf32-rounded out)
template<int BN, int EPI>
__global__ void __launch_bounds__(256)
mma_gemm(const float* __restrict__ A, const float* __restrict__ Bw,
         const float* __restrict__ bias, float* __restrict__ C, int N, int K)
{
    constexpr int NF = BN / 16;
    extern __shared__ float smem[];
    float acc[2][NF][4];
    #pragma unroll
    for (int i = 0; i < 2; i++)
        #pragma unroll
        for (int j = 0; j < NF; j++)
            #pragma unroll
            for (int q = 0; q < 4; q++) acc[i][j][q] = 0.f;

    int bm = blockIdx.y * 128, bn = blockIdx.x * BN;
    mma_core<BN>(A, Bw, smem, N, K, bm, bn, acc);

    int lane = threadIdx.x & 31, warp = threadIdx.x >> 5;
    int g = lane >> 2, tid4 = lane & 3;
    int wm = (warp >> 1) * 32, wn = (warp & 1) * (BN/2);

    #pragma unroll
    for (int mf = 0; mf < 2; mf++)
        #pragma unroll
        for (int nf = 0; nf < NF; nf++)
            #pragma unroll
            for (int r = 0; r < 2; r++)
                #pragma unroll
                for (int c = 0; c < 2; c++) {
                    int row = bm + wm + mf*16 + g + r*8;
                    int col = bn + wn + nf*8 + tid4*2 + c;
                    float v = acc[mf][nf][r*2 + c] + bias[col];
                    if (EPI == 1) v = roundtf(v / (1.f + __expf(-v)));
                    if (EPI == 2) v = roundtf(0.5f * v * (1.f + erff(v * 0.70710678118654752f)));
                    C[(size_t)row*N + col] = v;
                }
}

// Fused QKV: blockIdx.z selects {Wq,Wk,Wv}; epilogue remaps to [B,H,N,dk]
template<int BN>
__global__ void __launch_bounds__(256)
mma_gemm_qkv(const float* __restrict__ A,
             const float* Wq, const float* Wk, const float* Wv,
             const float* bq, const float* bk, const float* bv,
             float* oq, float* ok, float* ov)
{
    constexpr int NF = BN / 16;
    extern __shared__ float smem[];
    const float* Bw   = blockIdx.z == 0 ? Wq : (blockIdx.z == 1 ? Wk : Wv);
    const float* bias = blockIdx.z == 0 ? bq : (blockIdx.z == 1 ? bk : bv);
    float*       O    = blockIdx.z == 0 ? oq : (blockIdx.z == 1 ? ok : ov);

    float acc[2][NF][4];
    #pragma unroll
    for (int i = 0; i < 2; i++)
        #pragma unroll
        for (int j = 0; j < NF; j++)
            #pragma unroll
            for (int q = 0; q < 4; q++) acc[i][j][q] = 0.f;

    int bm = blockIdx.y * 128, bn = blockIdx.x * BN;
    mma_core<BN>(A, Bw, smem, Dn, Dn, bm, bn, acc);

    int lane = threadIdx.x & 31, warp = threadIdx.x >> 5;
    int g = lane >> 2, tid4 = lane & 3;
    int wm = (warp >> 1) * 32, wn = (warp & 1) * (BN/2);

    #pragma unroll
    for (int mf = 0; mf < 2; mf++)
        #pragma unroll
        for (int nf = 0; nf < NF; nf++)
            #pragma unroll
            for (int r = 0; r < 2; r++)
                #pragma unroll
                for (int c = 0; c < 2; c++) {
                    int row = bm + wm + mf*16 + g + r*8;
                    int col = bn + wn + nf*8 + tid4*2 + c;
                    float v = acc[mf][nf][r*2 + c] + bias[col];
                    int b = row >> 8, n = row & 255, h = col >> 5, d = col & 31;
                    O[((b*Hh + h)*Nn + n)*DK + d] = v;
                }
}

// ---------------- attention: per (b,h,scale) block, online softmax -----------
__global__ void __launch_bounds__(256)
attn_kernel()
{
    extern __shared__ float smem[];
    float* ksm   = smem;               // 8192
    float* vsm   = smem + 8192;        // 8192
    float* atile = smem + 16384;       // 256*33

    int kk = blockIdx.x;
    int h  = blockIdx.y;
    int b  = blockIdx.z;
    int t  = threadIdx.x;

    const float* kb = g_k + (size_t)(b*Hh + h)*Nn*DK;
    const float* vb = g_v + (size_t)(b*Hh + h)*Nn*DK;
    const float* qb = g_q + (size_t)(b*Hh + h)*Nn*DK;

    {
        const float4* k4 = (const float4*)kb;
        const float4* v4 = (const float4*)vb;
        float4* ks4 = (float4*)ksm;
        float4* vs4 = (float4*)vsm;
        #pragma unroll
        for (int i = 0; i < 8; i++) {
            ks4[i*256 + t] = k4[i*256 + t];
            vs4[i*256 + t] = v4[i*256 + t];
        }
    }
    float qreg[DK];
    {
        const float4* q4 = (const float4*)(qb + t*DK);
        #pragma unroll
        for (int i = 0; i < 8; i++) {
            float4 v = q4[i];
            qreg[i*4+0]=v.x; qreg[i*4+1]=v.y; qreg[i*4+2]=v.z; qreg[i*4+3]=v.w;
        }
    }
    __syncthreads();

    const float inv_sqrt = 0.17677669529663688f;
    float mx = -INFINITY, sum = 0.f;
    float accv[DK];
    #pragma unroll
    for (int d = 0; d < DK; d++) accv[d] = 0.f;

    const float* abase = g_acomb + (size_t)((b*Kk + kk)*Nn)*Nn;

    for (int m0 = 0; m0 < Nn; m0 += 32) {
        __syncthreads();
        #pragma unroll
        for (int i = 0; i < 32; i++) {
            int idx = i*256 + t;
            int nrow = idx >> 5, ml = idx & 31;
            atile[nrow*33 + ml] = abase[(size_t)nrow*Nn + m0 + ml];
        }
        __syncthreads();

        float sreg[32];
        float cmax = -INFINITY;
        #pragma unroll
        for (int ml = 0; ml < 32; ml++) {
            int m = m0 + ml;
            const float4* kr = (const float4*)(ksm + m*DK);
            float s = 0.f;
            #pragma unroll
            for (int i = 0; i < 8; i++) {
                float4 kv = kr[i];
                s += qreg[i*4+0]*kv.x + qreg[i*4+1]*kv.y
                   + qreg[i*4+2]*kv.z + qreg[i*4+3]*kv.w;
            }
            s = s * inv_sqrt + atile[t*33 + ml];
            sreg[ml] = s;
            cmax = fmaxf(cmax, s);
        }
        float newmax = fmaxf(mx, cmax);
        float corr = __expf(mx - newmax);
        sum *= corr;
        #pragma unroll
        for (int d = 0; d < DK; d++) accv[d] *= corr;
        #pragma unroll
        for (int ml = 0; ml < 32; ml++) {
            float p = __expf(sreg[ml] - newmax);
            sum += p;
            const float4* vr = (const float4*)(vsm + (m0+ml)*DK);
            #pragma unroll
            for (int i = 0; i < 8; i++) {
                float4 vv = vr[i];
                accv[i*4+0] += p*vv.x; accv[i*4+1] += p*vv.y;
                accv[i*4+2] += p*vv.z; accv[i*4+3] += p*vv.w;
            }
        }
        mx = newmax;
    }

    float inv = 1.f / sum;
    int khbase = (kk*Hh + h) * 4;
    #pragma unroll
    for (int d = 0; d < DK; d++) {
        int n2 = khbase + (d >> 3);
        int f  = (d & 7)*256 + t;
        g_msg[((size_t)(b*Nn) + n2)*2048 + f] = roundtf(accv[d]*inv);
    }
}

// ---------------- add-residual + LayerNorm (rows of 512) ---------------------
// out_r (optional) receives a tf32-rounded copy for downstream GEMM use.
__global__ void __launch_bounds__(256)
ln_kernel(const float* __restrict__ a, const float* __restrict__ resid,
          const float* __restrict__ g, const float* __restrict__ be,
          float* __restrict__ out, float* __restrict__ out_r)
{
    int row = blockIdx.x;
    int t   = threadIdx.x;
    const float* ap = a + (size_t)row*Dn;
    const float* rp = resid + (size_t)row*Dn;
    float v0 = ap[t]     + rp[t];
    float v1 = ap[t+256] + rp[t+256];

    float s  = v0 + v1;
    float sq = v0*v0 + v1*v1;
    #pragma unroll
    for (int o = 16; o > 0; o >>= 1) {
        s  += __shfl_xor_sync(0xffffffffu, s,  o);
        sq += __shfl_xor_sync(0xffffffffu, sq, o);
    }
    __shared__ float ws[8], wq[8], stat[2];
    int warp = t >> 5, lane = t & 31;
    if (lane == 0) { ws[warp] = s; wq[warp] = sq; }
    __syncthreads();
    if (t == 0) {
        float ts = 0.f, tq = 0.f;
        #pragma unroll
        for (int i = 0; i < 8; i++) { ts += ws[i]; tq += wq[i]; }
        float mean = ts * (1.f/Dn);
        float var  = tq * (1.f/Dn) - mean*mean;
        stat[0] = mean;
        stat[1] = rsqrtf(var + 1e-6f);
    }
    __syncthreads();
    float mean = stat[0], inv = stat[1];
    float o0 = (v0 - mean)*inv*g[t]       + be[t];
    float o1 = (v1 - mean)*inv*g[t+256]   + be[t+256];
    out[(size_t)row*Dn + t]       = o0;
    out[(size_t)row*Dn + t + 256] = o1;
    if (out_r) {
        out_r[(size_t)row*Dn + t]       = roundtf(o0);
        out_r[(size_t)row*Dn + t + 256] = roundtf(o1);
    }
}

// ---------------- launch ------------------------------------------------------
extern "C" void kernel_launch(void* const* d_in, const int* in_sizes, int n_in,
                              void* d_out, int out_size)
{
    const float* x    = (const float*)d_in[0];
    const float* dist = (const float*)d_in[1];
    const float* dbar = (const float*)d_in[2];
    const float* ab   = (const float*)d_in[3];
    const int*   mask = (const int*)  d_in[4];
    const float* Wq = (const float*)d_in[6],  *bq = (const float*)d_in[7];
    const float* Wk = (const float*)d_in[8],  *bk = (const float*)d_in[9];
    const float* Wv = (const float*)d_in[10], *bv = (const float*)d_in[11];
    const float* W1 = (const float*)d_in[12], *b1 = (const float*)d_in[13];
    const float* W2 = (const float*)d_in[14], *b2 = (const float*)d_in[15];
    const float* g1 = (const float*)d_in[16], *be1= (const float*)d_in[17];
    const float* Wf1= (const float*)d_in[18], *bf1= (const float*)d_in[19];
    const float* Wf2= (const float*)d_in[20], *bf2= (const float*)d_in[21];
    const float* g2 = (const float*)d_in[22], *be2= (const float*)d_in[23];
    float* out = (float*)d_out;

    float *pq, *pk, *pv, *pmsg, *ph1, *ph2, *py, *pyr, *pf1, *pf2;
    float *prx, *prwq, *prwk, *prwv, *prw1, *prw2, *prwf1, *prwf2;
    cudaGetSymbolAddress((void**)&pq,  g_q);
    cudaGetSymbolAddress((void**)&pk,  g_k);
    cudaGetSymbolAddress((void**)&pv,  g_v);
    cudaGetSymbolAddress((void**)&pmsg,g_msg);
    cudaGetSymbolAddress((void**)&ph1, g_h1);
    cudaGetSymbolAddress((void**)&ph2, g_h2);
    cudaGetSymbolAddress((void**)&py,  g_y);
    cudaGetSymbolAddress((void**)&pyr, g_yr);
    cudaGetSymbolAddress((void**)&pf1, g_f1);
    cudaGetSymbolAddress((void**)&pf2, g_f2);
    cudaGetSymbolAddress((void**)&prx,  g_rx);
    cudaGetSymbolAddress((void**)&prwq, g_rwq);
    cudaGetSymbolAddress((void**)&prwk, g_rwk);
    cudaGetSymbolAddress((void**)&prwv, g_rwv);
    cudaGetSymbolAddress((void**)&prw1, g_rw1);
    cudaGetSymbolAddress((void**)&prw2, g_rw2);
    cudaGetSymbolAddress((void**)&prwf1,g_rwf1);
    cudaGetSymbolAddress((void**)&prwf2,g_rwf2);

    const int ATTN_SMEM = (8192 + 8192 + 256*33) * 4;   // 99328 B
    // BN=64 gemm smem: (2*128*36 + 2*32*72)*4 = 55296 B
    const int GSMEM = (2*128*AS_STRIDE + 2*32*72) * 4;
    cudaFuncSetAttribute(attn_kernel,
                         cudaFuncAttributeMaxDynamicSharedMemorySize, ATTN_SMEM);
    cudaFuncSetAttribute(mma_gemm_qkv<64>,
                         cudaFuncAttributeMaxDynamicSharedMemorySize, GSMEM);
    cudaFuncSetAttribute(mma_gemm<64,0>,
                         cudaFuncAttributeMaxDynamicSharedMemorySize, GSMEM);
    cudaFuncSetAttribute(mma_gemm<64,1>,
                         cudaFuncAttributeMaxDynamicSharedMemorySize, GSMEM);
    cudaFuncSetAttribute(mma_gemm<64,2>,
                         cudaFuncAttributeMaxDynamicSharedMemorySize, GSMEM);

    // 0. pre-round weights + x to tf32 (one fused launch)
    {
        RoundArgs ra;
        ra.in[0]=x;   ra.out[0]=prx;   ra.n4[0]=MROWS*Dn/4;
        ra.in[1]=Wq;  ra.out[1]=prwq;  ra.n4[1]=Dn*Dn/4;
        ra.in[2]=Wk;  ra.out[2]=prwk;  ra.n4[2]=Dn*Dn/4;
        ra.in[3]=Wv;  ra.out[3]=prwv;  ra.n4[3]=Dn*Dn/4;
        ra.in[4]=W1;  ra.out[4]=prw1;  ra.n4[4]=2048*Dn/4;
        ra.in[5]=W2;  ra.out[5]=prw2;  ra.n4[5]=Dn*Dn/4;
        ra.in[6]=Wf1; ra.out[6]=prwf1; ra.n4[6]=Dn*FFN/4;
        ra.in[7]=Wf2; ra.out[7]=prwf2; ra.n4[7]=FFN*Dn/4;
        round_kernel<<<dim3(256, 8), 256>>>(ra);
    }

    // 1. combined bias/mask
    prep_acomb<<<dim3(Bn*Kk, Nn), 256>>>(dist, dbar, ab, mask);

    // 2. fused QKV projections -> [B,H,N,dk]
    mma_gemm_qkv<64><<<dim3(Dn/64, MROWS/128, 3), 256, GSMEM>>>(
        prx, prwq, prwk, prwv, bq, bk, bv, pq, pk, pv);

    // 3. attention (writes scrambled, tf32-rounded msg2)
    attn_kernel<<<dim3(Kk, Hh, Bn), 256, ATTN_SMEM>>>();

    // 4. h1 = silu(msg2 @ W1 + b1)   grid 8x16 = 128
    mma_gemm<64,1><<<dim3(Dn/64, MROWS/128), 256, GSMEM>>>(pmsg, prw1, b1, ph1, Dn, 2048);
    // 5. h2 = h1 @ W2 + b2           grid 128
    mma_gemm<64,0><<<dim3(Dn/64, MROWS/128), 256, GSMEM>>>(ph1, prw2, b2, ph2, Dn, Dn);
    // 6. y = LN(h2 + x), plus rounded copy
    ln_kernel<<<MROWS, 256>>>(ph2, x, g1, be1, py, pyr);
    // 7. f1 = gelu(y @ Wf1 + bf1)    grid 32x16 = 512
    mma_gemm<64,2><<<dim3(FFN/64, MROWS/128), 256, GSMEM>>>(pyr, prwf1, bf1, pf1, FFN, Dn);
    // 8. f2 = f1 @ Wf2 + bf2         grid 128
    mma_gemm<64,0><<<dim3(Dn/64, MROWS/128), 256, GSMEM>>>(pf1, prwf2, bf2, pf2, Dn, 2048);
    // 9. out = LN(f2 + y)
    ln_kernel<<<MROWS, 256>>>(pf2, py, g2, be2, out, nullptr);
}

// round 8
// speedup vs baseline: 2.5612x; 1.2770x over previous
#include <cuda_runtime.h>
#include <cuda_bf16.h>
#include <math.h>
#include <stdint.h>

// Problem constants
#define Bn 8
#define Nn 256
#define Dn 512
#define Hh 16
#define Kk 4
#define DK 32
#define FFN 2048
#define MROWS (Bn*Nn)          // 2048
#define NEGV (-1e12f)

// ---------------- scratch (device globals; no allocation allowed) -------------
__device__ float g_q[Bn*Hh*Nn*DK];        // [B,H,N,dk]
__device__ float g_k[Bn*Hh*Nn*DK];
__device__ float g_v[Bn*Hh*Nn*DK];
__device__ float g_s0[Bn*Hh*Nn*Nn];       // raw scores q.k/sqrt(dk)  [B*H,N,N]
__device__ float g_acomb[Bn*Kk*Nn*Nn];    // combined bias+mask
__device__ float g_msg[MROWS*2048];       // scrambled msg2 (tf32-rounded)
__device__ float g_h1[MROWS*Dn];
__device__ float g_h2[MROWS*Dn];
__device__ float g_y [MROWS*Dn];
__device__ float g_yr[MROWS*Dn];
__device__ float g_f1[MROWS*FFN];
__device__ float g_f2[MROWS*Dn];
// tf32-rounded operand copies
__device__ float g_rx [MROWS*Dn];
__device__ float g_rwq[Dn*Dn];
__device__ float g_rwk[Dn*Dn];
__device__ float g_rwv[Dn*Dn];
__device__ float g_rw1[2048*Dn];
__device__ float g_rw2[Dn*Dn];
__device__ float g_rwf1[Dn*FFN];
__device__ float g_rwf2[FFN*Dn];

__device__ __forceinline__ uint32_t f2tf(float f) {
    uint32_t r; asm("cvt.rna.tf32.f32 %0, %1;" : "=r"(r) : "f"(f)); return r;
}
__device__ __forceinline__ float roundtf(float f) { return __uint_as_float(f2tf(f)); }

// ---------------- tf32 pre-rounding pass (8 tensors in one launch) ------------
struct RoundArgs {
    const float* in[8];
    float*       out[8];
    int          n4[8];
};
__global__ void __launch_bounds__(256)
round_kernel(RoundArgs a)
{
    int j = blockIdx.y;
    const float4* in  = (const float4*)a.in[j];
    float4*       out = (float4*)a.out[j];
    int n4 = a.n4[j];
    for (int i = blockIdx.x*256 + threadIdx.x; i < n4; i += gridDim.x*256) {
        float4 v = in[i];
        v.x = roundtf(v.x); v.y = roundtf(v.y);
        v.z = roundtf(v.z); v.w = roundtf(v.w);
        out[i] = v;
    }
}

// ---------------- prep: combined bias + padding mask + distance mask ---------
__global__ void prep_acomb(const float* __restrict__ dist,
                           const float* __restrict__ dist_bar,
                           const float* __restrict__ bias,
                           const int*   __restrict__ mask)
{
    int n  = blockIdx.y;
    int bk = blockIdx.x;
    int b  = bk >> 2, kk = bk & 3;
    int m  = threadIdx.x;

    int mv = mask[(b*Nn + n)*Nn + m];
    bool dist_ok;
    if (n == 0 || m == 0) dist_ok = true;
    else dist_ok = dist[b*255*255 + (n-1)*255 + (m-1)] < dist_bar[kk];

    float val;
    if (mv != 0 && dist_ok)
        val = bias[((b*Kk + kk)*Nn + n)*Nn + m];
    else
        val = NEGV;
    g_acomb[((b*Kk + kk)*Nn + n)*Nn + m] = val;
}

// =====================  tf32 tensor-core GEMM  ================================
#define AS_STRIDE 36
#define AS_TILE (128*AS_STRIDE)

__device__ __forceinline__ uint32_t cvta_s(const void* p) {
    return (uint32_t)__cvta_generic_to_shared(p);
}
#define CPA16(dst, src) \
    asm volatile("cp.async.cg.shared.global [%0], [%1], 16;" :: "r"(dst), "l"(src))

__device__ __forceinline__ void mma8(float c[4], const uint32_t a[4], const uint32_t b[2]) {
    asm volatile(
      "mma.sync.aligned.m16n8k8.row.col.f32.tf32.tf32.f32 "
      "{%0,%1,%2,%3},{%4,%5,%6,%7},{%8,%9},{%0,%1,%2,%3};"
      : "+f"(c[0]), "+f"(c[1]), "+f"(c[2]), "+f"(c[3])
      : "r"(a[0]), "r"(a[1]), "r"(a[2]), "r"(a[3]), "r"(b[0]), "r"(b[1]));
}

template<int BN>
__device__ __forceinline__ void mma_core(const float* __restrict__ A,
                                         const float* __restrict__ Bw,
                                         float* smem, int N, int K,
                                         int bm, int bn, float acc[2][BN/16][4])
{
    constexpr int BS_STRIDE = BN + 8;
    constexpr int BS_TILE   = 32 * BS_STRIDE;
    constexpr int NF        = BN / 16;

    float* As = smem;
    float* Bs = smem + 2*AS_TILE;
    int t = threadIdx.x, lane = t & 31, warp = t >> 5;
    int g = lane >> 2, tid4 = lane & 3;
    int wm = (warp >> 1) * 32, wn = (warp & 1) * (BN/2);

    int T = K / 32;

    auto copy_tile = [&](int kt, int buf) {
        float* Ad = As + buf*AS_TILE;
        float* Bd = Bs + buf*BS_TILE;
        int k0 = kt * 32;
        #pragma unroll
        for (int i = 0; i < 4; i++) {
            int idx = t + i*256;
            int row = idx >> 3, f4 = (idx & 7) * 4;
            CPA16(cvta_s(Ad + row*AS_STRIDE + f4),
                  A + (size_t)(bm + row)*K + k0 + f4);
        }
        #pragma unroll
        for (int i = 0; i < BN/32; i++) {
            int idx = t + i*256;
            int r = idx / (BN/4), f4 = (idx % (BN/4)) * 4;
            CPA16(cvta_s(Bd + r*BS_STRIDE + f4),
                  Bw + (size_t)(k0 + r)*N + bn + f4);
        }
        asm volatile("cp.async.commit_group;");
    };

    copy_tile(0, 0);
    for (int kt = 0; kt < T; kt++) {
        int buf = kt & 1;
        if (kt + 1 < T) {
            copy_tile(kt + 1, buf ^ 1);
            asm volatile("cp.async.wait_group 1;");
        } else {
            asm volatile("cp.async.wait_group 0;");
        }
        __syncthreads();

        const uint32_t* Ab = (const uint32_t*)(As + buf*AS_TILE);
        const uint32_t* Bb = (const uint32_t*)(Bs + buf*BS_TILE);
        #pragma unroll
        for (int ks = 0; ks < 4; ks++) {
            int kk = ks * 8;
            uint32_t af[2][4], bf[NF][2];
            #pragma unroll
            for (int mf = 0; mf < 2; mf++) {
                const uint32_t* p = Ab + (wm + mf*16 + g)*AS_STRIDE + kk + tid4;
                af[mf][0] = p[0];
                af[mf][1] = p[8*AS_STRIDE];
                af[mf][2] = p[4];
                af[mf][3] = p[8*AS_STRIDE + 4];
            }
            #pragma unroll
            for (int nf = 0; nf < NF; nf++) {
                const uint32_t* p = Bb + (kk + tid4)*BS_STRIDE + wn + nf*8 + g;
                bf[nf][0] = p[0];
                bf[nf][1] = p[4*BS_STRIDE];
            }
            #pragma unroll
            for (int mf = 0; mf < 2; mf++)
                #pragma unroll
                for (int nf = 0; nf < NF; nf++)
                    mma8(acc[mf][nf], af[mf], bf[nf]);
        }
        __syncthreads();
    }
}

// EPI: 0 = none, 1 = silu (tf32 out), 2 = gelu (tf32 out)
template<int BN, int EPI>
__global__ void __launch_bounds__(256)
mma_gemm(const float* __restrict__ A, const float* __restrict__ Bw,
         const float* __restrict__ bias, float* __restrict__ C, int N, int K)
{
    constexpr int NF = BN / 16;
    extern __shared__ float smem[];
    float acc[2][NF][4];
    #pragma unroll
    for (int i = 0; i < 2; i++)
        #pragma unroll
        for (int j = 0; j < NF; j++)
            #pragma unroll
            for (int q = 0; q < 4; q++) acc[i][j][q] = 0.f;

    int bm = blockIdx.y * 128, bn = blockIdx.x * BN;
    mma_core<BN>(A, Bw, smem, N, K, bm, bn, acc);

    int lane = threadIdx.x & 31, warp = threadIdx.x >> 5;
    int g = lane >> 2, tid4 = lane & 3;
    int wm = (warp >> 1) * 32, wn = (warp & 1) * (BN/2);

    #pragma unroll
    for (int mf = 0; mf < 2; mf++)
        #pragma unroll
        for (int nf = 0; nf < NF; nf++)
            #pragma unroll
            for (int r = 0; r < 2; r++)
                #pragma unroll
                for (int c = 0; c < 2; c++) {
                    int row = bm + wm + mf*16 + g + r*8;
                    int col = bn + wn + nf*8 + tid4*2 + c;
                    float v = acc[mf][nf][r*2 + c] + bias[col];
                    if (EPI == 1) v = roundtf(v / (1.f + __expf(-v)));
                    if (EPI == 2) v = roundtf(0.5f * v * (1.f + erff(v * 0.70710678118654752f)));
                    C[(size_t)row*N + col] = v;
                }
}

// Fused QKV: blockIdx.z selects {Wq,Wk,Wv}; epilogue remaps to [B,H,N,dk]
template<int BN>
__global__ void __launch_bounds__(256)
mma_gemm_qkv(const float* __restrict__ A,
             const float* Wq, const float* Wk, const float* Wv,
             const float* bq, const float* bk, const float* bv,
             float* oq, float* ok, float* ov)
{
    constexpr int NF = BN / 16;
    extern __shared__ float smem[];
    const float* Bw   = blockIdx.z == 0 ? Wq : (blockIdx.z == 1 ? Wk : Wv);
    const float* bias = blockIdx.z == 0 ? bq : (blockIdx.z == 1 ? bk : bv);
    float*       O    = blockIdx.z == 0 ? oq : (blockIdx.z == 1 ? ok : ov);

    float acc[2][NF][4];
    #pragma unroll
    for (int i = 0; i < 2; i++)
        #pragma unroll
        for (int j = 0; j < NF; j++)
            #pragma unroll
            for (int q = 0; q < 4; q++) acc[i][j][q] = 0.f;

    int bm = blockIdx.y * 128, bn = blockIdx.x * BN;
    mma_core<BN>(A, Bw, smem, Dn, Dn, bm, bn, acc);

    int lane = threadIdx.x & 31, warp = threadIdx.x >> 5;
    int g = lane >> 2, tid4 = lane & 3;
    int wm = (warp >> 1) * 32, wn = (warp & 1) * (BN/2);

    #pragma unroll
    for (int mf = 0; mf < 2; mf++)
        #pragma unroll
        for (int nf = 0; nf < NF; nf++)
            #pragma unroll
            for (int r = 0; r < 2; r++)
                #pragma unroll
                for (int c = 0; c < 2; c++) {
                    int row = bm + wm + mf*16 + g + r*8;
                    int col = bn + wn + nf*8 + tid4*2 + c;
                    float v = acc[mf][nf][r*2 + c] + bias[col];
                    int b = row >> 8, n = row & 255, h = col >> 5, d = col & 31;
                    O[((b*Hh + h)*Nn + n)*DK + d] = v;
                }
}

// ---------------- QK^T score kernel (tf32 mma, batched over b*h) --------------
// S0[bh, n, m] = (1/sqrt(dk)) * sum_d Q[bh,n,d] * K[bh,m,d]
// Block: 128x128 tile of one bh. 256 threads, 8 warps (4x2), warptile 32x64.
__global__ void __launch_bounds__(256)
qk_kernel()
{
    __shared__ float Qs[128*AS_STRIDE];
    __shared__ float Ks[128*AS_STRIDE];

    int bh = blockIdx.z;
    int bm = blockIdx.y * 128;   // query rows
    int bn = blockIdx.x * 128;   // key rows
    const float* Qg = g_q + (size_t)bh*Nn*DK;
    const float* Kg = g_k + (size_t)bh*Nn*DK;

    int t = threadIdx.x, lane = t & 31, warp = t >> 5;
    int g = lane >> 2, tid4 = lane & 3;
    int wm = (warp >> 1) * 32, wn = (warp & 1) * 64;

    // load Q tile [128 x 32] and K tile [128 x 32]
    #pragma unroll
    for (int i = 0; i < 4; i++) {
        int idx = t + i*256;
        int row = idx >> 3, f4 = (idx & 7) * 4;
        CPA16(cvta_s(Qs + row*AS_STRIDE + f4), Qg + (size_t)(bm+row)*DK + f4);
        CPA16(cvta_s(Ks + row*AS_STRIDE + f4), Kg + (size_t)(bn+row)*DK + f4);
    }
    asm volatile("cp.async.commit_group;");
    asm volatile("cp.async.wait_group 0;");
    __syncthreads();

    float acc[2][8][4];
    #pragma unroll
    for (int i = 0; i < 2; i++)
        #pragma unroll
        for (int j = 0; j < 8; j++)
            #pragma unroll
            for (int q = 0; q < 4; q++) acc[i][j][q] = 0.f;

    const uint32_t* Qb = (const uint32_t*)Qs;
    const uint32_t* Kb = (const uint32_t*)Ks;
    #pragma unroll
    for (int ks = 0; ks < 4; ks++) {
        int kk = ks * 8;
        uint32_t af[2][4], bf[8][2];
        #pragma unroll
        for (int mf = 0; mf < 2; mf++) {
            const uint32_t* p = Qb + (wm + mf*16 + g)*AS_STRIDE + kk + tid4;
            af[mf][0] = f2tf(__uint_as_float(p[0]));
            af[mf][1] = f2tf(__uint_as_float(p[8*AS_STRIDE]));
            af[mf][2] = f2tf(__uint_as_float(p[4]));
            af[mf][3] = f2tf(__uint_as_float(p[8*AS_STRIDE + 4]));
        }
        #pragma unroll
        for (int nf = 0; nf < 8; nf++) {
            // B[k=d][n=m] = K[m][d]  (transposed access, stride 36 -> conflict-free)
            const uint32_t* p = Kb + (wn + nf*8 + g)*AS_STRIDE + kk + tid4;
            bf[nf][0] = f2tf(__uint_as_float(p[0]));
            bf[nf][1] = f2tf(__uint_as_float(p[4]));
        }
        #pragma unroll
        for (int mf = 0; mf < 2; mf++)
            #pragma unroll
            for (int nf = 0; nf < 8; nf++)
                mma8(acc[mf][nf], af[mf], bf[nf]);
    }

    const float inv_sqrt = 0.17677669529663688f;
    float* Sg = g_s0 + (size_t)bh*Nn*Nn;
    #pragma unroll
    for (int mf = 0; mf < 2; mf++)
        #pragma unroll
        for (int nf = 0; nf < 8; nf++)
            #pragma unroll
            for (int r = 0; r < 2; r++)
                #pragma unroll
                for (int c = 0; c < 2; c++) {
                    int row = bm + wm + mf*16 + g + r*8;
                    int col = bn + wn + nf*8 + tid4*2 + c;
                    Sg[(size_t)row*Nn + col] = acc[mf][nf][r*2 + c] * inv_sqrt;
                }
}

// ---------------- attention: softmax + PV (scores precomputed) ---------------
// smem: vsm[256*32] + atile[256*33] = 66560 B.  2 CTAs/SM.
__global__ void __launch_bounds__(256)
attn_kernel()
{
    extern __shared__ float smem[];
    float* vsm   = smem;               // 8192 floats
    float* atile = smem + 8192;        // 256*33

    int kk = blockIdx.x;
    int h  = blockIdx.y;
    int b  = blockIdx.z;
    int t  = threadIdx.x;              // query row

    const float* vb = g_v + (size_t)(b*Hh + h)*Nn*DK;
    {
        const float4* v4 = (const float4*)vb;
        float4* vs4 = (float4*)vsm;
        #pragma unroll
        for (int i = 0; i < 8; i++)
            vs4[i*256 + t] = v4[i*256 + t];
    }

    float mx = -INFINITY, sum = 0.f;
    float accv[DK];
    #pragma unroll
    for (int d = 0; d < DK; d++) accv[d] = 0.f;

    const float* abase = g_acomb + (size_t)((b*Kk + kk)*Nn)*Nn;
    const float* sbase = g_s0    + (size_t)((b*Hh + h)*Nn)*Nn;

    for (int m0 = 0; m0 < Nn; m0 += 32) {
        __syncthreads();
        // stage combined scores: S0 + acomb (both coalesced)
        #pragma unroll
        for (int i = 0; i < 32; i++) {
            int idx = i*256 + t;
            int nrow = idx >> 5, ml = idx & 31;
            size_t off = (size_t)nrow*Nn + m0 + ml;
            atile[nrow*33 + ml] = sbase[off] + abase[off];
        }
        __syncthreads();

        float sreg[32];
        float cmax = -INFINITY;
        #pragma unroll
        for (int ml = 0; ml < 32; ml++) {
            float s = atile[t*33 + ml];
            sreg[ml] = s;
            cmax = fmaxf(cmax, s);
        }
        float newmax = fmaxf(mx, cmax);
        float corr = __expf(mx - newmax);
        sum *= corr;
        #pragma unroll
        for (int d = 0; d < DK; d++) accv[d] *= corr;
        #pragma unroll
        for (int ml = 0; ml < 32; ml++) {
            float p = __expf(sreg[ml] - newmax);
            sum += p;
            const float4* vr = (const float4*)(vsm + (m0+ml)*DK);
            #pragma unroll
            for (int i = 0; i < 8; i++) {
                float4 vv = vr[i];
                accv[i*4+0] += p*vv.x; accv[i*4+1] += p*vv.y;
                accv[i*4+2] += p*vv.z; accv[i*4+3] += p*vv.w;
            }
        }
        mx = newmax;
    }

    float inv = 1.f / sum;
    int khbase = (kk*Hh + h) * 4;
    #pragma unroll
    for (int d = 0; d < DK; d++) {
        int n2 = khbase + (d >> 3);
        int f  = (d & 7)*256 + t;
        g_msg[((size_t)(b*Nn) + n2)*2048 + f] = roundtf(accv[d]*inv);
    }
}

// ---------------- add-residual + LayerNorm (rows of 512) ---------------------
__global__ void __launch_bounds__(256)
ln_kernel(const float* __restrict__ a, const float* __restrict__ resid,
          const float* __restrict__ g, const float* __restrict__ be,
          float* __restrict__ out, float* __restrict__ out_r)
{
    int row = blockIdx.x;
    int t   = threadIdx.x;
    const float* ap = a + (size_t)row*Dn;
    const float* rp = resid + (size_t)row*Dn;
    float v0 = ap[t]     + rp[t];
    float v1 = ap[t+256] + rp[t+256];

    float s  = v0 + v1;
    float sq = v0*v0 + v1*v1;
    #pragma unroll
    for (int o = 16; o > 0; o >>= 1) {
        s  += __shfl_xor_sync(0xffffffffu, s,  o);
        sq += __shfl_xor_sync(0xffffffffu, sq, o);
    }
    __shared__ float ws[8], wq[8], stat[2];
    int warp = t >> 5, lane = t & 31;
    if (lane == 0) { ws[warp] = s; wq[warp] = sq; }
    __syncthreads();
    if (t == 0) {
        float ts = 0.f, tq = 0.f;
        #pragma unroll
        for (int i = 0; i < 8; i++) { ts += ws[i]; tq += wq[i]; }
        float mean = ts * (1.f/Dn);
        float var  = tq * (1.f/Dn) - mean*mean;
        stat[0] = mean;
        stat[1] = rsqrtf(var + 1e-6f);
    }
    __syncthreads();
    float mean = stat[0], inv = stat[1];
    float o0 = (v0 - mean)*inv*g[t]       + be[t];
    float o1 = (v1 - mean)*inv*g[t+256]   + be[t+256];
    out[(size_t)row*Dn + t]       = o0;
    out[(size_t)row*Dn + t + 256] = o1;
    if (out_r) {
        out_r[(size_t)row*Dn + t]       = roundtf(o0);
        out_r[(size_t)row*Dn + t + 256] = roundtf(o1);
    }
}

// ---------------- launch ------------------------------------------------------
extern "C" void kernel_launch(void* const* d_in, const int* in_sizes, int n_in,
                              void* d_out, int out_size)
{
    const float* x    = (const float*)d_in[0];
    const float* dist = (const float*)d_in[1];
    const float* dbar = (const float*)d_in[2];
    const float* ab   = (const float*)d_in[3];
    const int*   mask = (const int*)  d_in[4];
    const float* Wq = (const float*)d_in[6],  *bq = (const float*)d_in[7];
    const float* Wk = (const float*)d_in[8],  *bk = (const float*)d_in[9];
    const float* Wv = (const float*)d_in[10], *bv = (const float*)d_in[11];
    const float* W1 = (const float*)d_in[12], *b1 = (const float*)d_in[13];
    const float* W2 = (const float*)d_in[14], *b2 = (const float*)d_in[15];
    const float* g1 = (const float*)d_in[16], *be1= (const float*)d_in[17];
    const float* Wf1= (const float*)d_in[18], *bf1= (const float*)d_in[19];
    const float* Wf2= (const float*)d_in[20], *bf2= (const float*)d_in[21];
    const float* g2 = (const float*)d_in[22], *be2= (const float*)d_in[23];
    float* out = (float*)d_out;

    float *pq, *pk, *pv, *pmsg, *ph1, *ph2, *py, *pyr, *pf1, *pf2;
    float *prx, *prwq, *prwk, *prwv, *prw1, *prw2, *prwf1, *prwf2;
    cudaGetSymbolAddress((void**)&pq,  g_q);
    cudaGetSymbolAddress((void**)&pk,  g_k);
    cudaGetSymbolAddress((void**)&pv,  g_v);
    cudaGetSymbolAddress((void**)&pmsg,g_msg);
    cudaGetSymbolAddress((void**)&ph1, g_h1);
    cudaGetSymbolAddress((void**)&ph2, g_h2);
    cudaGetSymbolAddress((void**)&py,  g_y);
    cudaGetSymbolAddress((void**)&pyr, g_yr);
    cudaGetSymbolAddress((void**)&pf1, g_f1);
    cudaGetSymbolAddress((void**)&pf2, g_f2);
    cudaGetSymbolAddress((void**)&prx,  g_rx);
    cudaGetSymbolAddress((void**)&prwq, g_rwq);
    cudaGetSymbolAddress((void**)&prwk, g_rwk);
    cudaGetSymbolAddress((void**)&prwv, g_rwv);
    cudaGetSymbolAddress((void**)&prw1, g_rw1);
    cudaGetSymbolAddress((void**)&prw2, g_rw2);
    cudaGetSymbolAddress((void**)&prwf1,g_rwf1);
    cudaGetSymbolAddress((void**)&prwf2,g_rwf2);

    const int ATTN_SMEM = (Nn*DK + Nn*33) * 4;           // 66560 B
    const int GSMEM = (2*128*AS_STRIDE + 2*32*72) * 4;   // 55296 B
    cudaFuncSetAttribute(attn_kernel,
                         cudaFuncAttributeMaxDynamicSharedMemorySize, ATTN_SMEM);
    cudaFuncSetAttribute(mma_gemm_qkv<64>,
                         cudaFuncAttributeMaxDynamicSharedMemorySize, GSMEM);
    cudaFuncSetAttribute(mma_gemm<64,0>,
                         cudaFuncAttributeMaxDynamicSharedMemorySize, GSMEM);
    cudaFuncSetAttribute(mma_gemm<64,1>,
                         cudaFuncAttributeMaxDynamicSharedMemorySize, GSMEM);
    cudaFuncSetAttribute(mma_gemm<64,2>,
                         cudaFuncAttributeMaxDynamicSharedMemorySize, GSMEM);

    // 0. pre-round weights + x to tf32
    {
        RoundArgs ra;
        ra.in[0]=x;   ra.out[0]=prx;   ra.n4[0]=MROWS*Dn/4;
        ra.in[1]=Wq;  ra.out[1]=prwq;  ra.n4[1]=Dn*Dn/4;
        ra.in[2]=Wk;  ra.out[2]=prwk;  ra.n4[2]=Dn*Dn/4;
        ra.in[3]=Wv;  ra.out[3]=prwv;  ra.n4[3]=Dn*Dn/4;
        ra.in[4]=W1;  ra.out[4]=prw1;  ra.n4[4]=2048*Dn/4;
        ra.in[5]=W2;  ra.out[5]=prw2;  ra.n4[5]=Dn*Dn/4;
        ra.in[6]=Wf1; ra.out[6]=prwf1; ra.n4[6]=Dn*FFN/4;
        ra.in[7]=Wf2; ra.out[7]=prwf2; ra.n4[7]=FFN*Dn/4;
        round_kernel<<<dim3(256, 8), 256>>>(ra);
    }

    // 1. combined bias/mask
    prep_acomb<<<dim3(Bn*Kk, Nn), 256>>>(dist, dbar, ab, mask);

    // 2. fused QKV projections -> [B,H,N,dk]
    mma_gemm_qkv<64><<<dim3(Dn/64, MROWS/128, 3), 256, GSMEM>>>(
        prx, prwq, prwk, prwv, bq, bk, bv, pq, pk, pv);

    // 3a. raw scores S0 = QK^T/sqrt(dk)   (tensor cores, 512 blocks)
    qk_kernel<<<dim3(2, 2, Bn*Hh), 256>>>();

    // 3b. attention: softmax + PV (writes scrambled, tf32-rounded msg2)
    attn_kernel<<<dim3(Kk, Hh, Bn), 256, ATTN_SMEM>>>();

    // 4. h1 = silu(msg2 @ W1 + b1)
    mma_gemm<64,1><<<dim3(Dn/64, MROWS/128), 256, GSMEM>>>(pmsg, prw1, b1, ph1, Dn, 2048);
    // 5. h2 = h1 @ W2 + b2
    mma_gemm<64,0><<<dim3(Dn/64, MROWS/128), 256, GSMEM>>>(ph1, prw2, b2, ph2, Dn, Dn);
    // 6. y = LN(h2 + x), plus rounded copy
    ln_kernel<<<MROWS, 256>>>(ph2, x, g1, be1, py, pyr);
    // 7. f1 = gelu(y @ Wf1 + bf1)
    mma_gemm<64,2><<<dim3(FFN/64, MROWS/128), 256, GSMEM>>>(pyr, prwf1, bf1, pf1, FFN, Dn);
    // 8. f2 = f1 @ Wf2 + bf2
    mma_gemm<64,0><<<dim3(Dn/64, MROWS/128), 256, GSMEM>>>(pf1, prwf2, bf2, pf2, Dn, 2048);
    // 9. out = LN(f2 + y)
    ln_kernel<<<MROWS, 256>>>(pf2, py, g2, be2, out, nullptr);
}